// round 5
// baseline (speedup 1.0000x reference)
#include <cuda_runtime.h>
#include <cuda_bf16.h>

// PatternAwareLoss: mean over (B,S,L) of boost*mask*(softplus(x) - x*y) / sum(mask)
// B=64, S=8192, L=24. boost[b,s]=1.2 if any-label(s) && any-label(s+1) && s<S-1.
//
// R4: single fused kernel. Main pass is HBM-bound (~7.2TB/s of 8TB/s); the old
// separate 1-block reduce kernel cost 10.6us (42% of runtime) in pure launch +
// latency overhead. Replaced with threadfence last-block-done reduction:
// every block writes one float2 partial + bumps a ticket; the last block
// re-reads all partials from L2 and finalizes. Ticket counter is statically 0
// and reset by the last block -> graph-replay safe, deterministic, alloc-free.

#define NPOS   (64 * 8192)     // B*S
#define S_LEN  8192
#define L_DIM  24
#define TPB    256
#define NBLK   (NPOS / TPB)    // 2048

__device__ float2       g_part[NBLK];
__device__ unsigned int g_ticket = 0;   // self-resetting; 0 at module load

__device__ __forceinline__ void proc_elem(float x, int y, float& sm, float& sl) {
    // sl += log2(1 + exp(-|x|));  sm += max(x,0) - x*y
    float a = fabsf(x);
    float e = __expf(-a);              // FMUL + MUFU.EX2
    sl += __log2f(1.0f + e);           // FADD + MUFU.LG2 (ln2 scale hoisted)
    sm += fmaxf(x, 0.0f) - x * (float)y;
}

__global__ __launch_bounds__(TPB) void loss_fused_kernel(
    const float* __restrict__ logits,
    const int*   __restrict__ labels,
    const float* __restrict__ attn_mask,
    float*       __restrict__ out)
{
    const int p = blockIdx.x * TPB + threadIdx.x;   // position index in [0, NPOS)
    const unsigned lane = threadIdx.x & 31u;

    const float4* __restrict__ lg4 = reinterpret_cast<const float4*>(logits + (size_t)p * L_DIM);
    const int4*   __restrict__ lb4 = reinterpret_cast<const int4*>(labels + (size_t)p * L_DIM);

    // 4 parallel accumulator pairs for ILP across the dependent-add chains.
    float sm0 = 0.f, sm1 = 0.f, sm2 = 0.f, sm3 = 0.f;
    float sl0 = 0.f, sl1 = 0.f, sl2 = 0.f, sl3 = 0.f;
    int   orr = 0;

#pragma unroll
    for (int i = 0; i < L_DIM / 4; i++) {   // 6 iterations
        float4 x = lg4[i];
        int4   y = lb4[i];
        orr |= (y.x | y.y | y.z | y.w);
        proc_elem(x.x, y.x, sm0, sl0);
        proc_elem(x.y, y.y, sm1, sl1);
        proc_elem(x.z, y.z, sm2, sl2);
        proc_elem(x.w, y.w, sm3, sl3);
    }

    float sm = (sm0 + sm1) + (sm2 + sm3);
    float sl = (sl0 + sl1) + (sl2 + sl3);
    float possum = fmaf(0.69314718055994531f, sl, sm);   // ln2*sum(log2) + sum(relu - xy)

    int hp = (orr != 0) ? 1 : 0;

    // hp of position p+1: neighbor lane; lane 31 halo-loads the next position.
    int hp_next = __shfl_down_sync(0xffffffffu, hp, 1);
    if (lane == 31u) {
        hp_next = 0;
        if (((p + 1) & (S_LEN - 1)) != 0) {   // p+1 in same batch (also guards global end)
            const int4* nb4 = reinterpret_cast<const int4*>(labels + (size_t)(p + 1) * L_DIM);
            int o2 = 0;
#pragma unroll
            for (int i = 0; i < L_DIM / 4; i++) {
                int4 t = nb4[i];
                o2 |= (t.x | t.y | t.z | t.w);
            }
            hp_next = (o2 != 0) ? 1 : 0;
        }
    }

    const int s_in_batch = p & (S_LEN - 1);
    const float boost = (s_in_batch != (S_LEN - 1) && hp && hp_next) ? 1.2f : 1.0f;
    const float m = attn_mask[p];

    float num = m * boost * possum;
    float den = m;

    // warp reduce (pairwise, deterministic)
#pragma unroll
    for (int off = 16; off > 0; off >>= 1) {
        num += __shfl_down_sync(0xffffffffu, num, off);
        den += __shfl_down_sync(0xffffffffu, den, off);
    }

    __shared__ float2 wsum[TPB / 32];
    __shared__ bool   s_is_last;
    if (lane == 0) wsum[threadIdx.x >> 5] = make_float2(num, den);
    __syncthreads();

    if (threadIdx.x == 0) {
        float n = 0.f, d = 0.f;
#pragma unroll
        for (int i = 0; i < TPB / 32; i++) { n += wsum[i].x; d += wsum[i].y; }
        g_part[blockIdx.x] = make_float2(n, d);
        __threadfence();                              // partial visible before ticket
        unsigned t = atomicAdd(&g_ticket, 1u);
        s_is_last = (t == (unsigned)(NBLK - 1));
    }
    __syncthreads();

    if (!s_is_last) return;

    // ── Last block: final reduction over all 2048 partials (L2-resident). ──
    __threadfence();   // acquire: order partial reads after ticket observation
    double n = 0.0, d = 0.0;
#pragma unroll 4
    for (int i = threadIdx.x; i < NBLK; i += TPB) {   // 8 independent loads/thread
        float2 v = g_part[i];
        n += (double)v.x;
        d += (double)v.y;
    }

    __shared__ double sn[TPB];
    __shared__ double sd[TPB];
    sn[threadIdx.x] = n;
    sd[threadIdx.x] = d;
    __syncthreads();
#pragma unroll
    for (int s = TPB / 2; s > 0; s >>= 1) {
        if (threadIdx.x < s) {
            sn[threadIdx.x] += sn[threadIdx.x + s];
            sd[threadIdx.x] += sd[threadIdx.x + s];
        }
        __syncthreads();
    }
    if (threadIdx.x == 0) {
        out[0] = (float)(sn[0] / sd[0]);
        g_ticket = 0;                                 // reset for next graph replay
    }
}

extern "C" void kernel_launch(void* const* d_in, const int* in_sizes, int n_in,
                              void* d_out, int out_size)
{
    const float* logits = (const float*)d_in[0];
    const int*   labels = (const int*)d_in[1];
    const float* amask  = (const float*)d_in[2];
    float* out = (float*)d_out;

    loss_fused_kernel<<<NBLK, TPB>>>(logits, labels, amask, out);
}

// round 6
// speedup vs baseline: 1.0047x; 1.0047x over previous
#include <cuda_runtime.h>
#include <cuda_bf16.h>

// PatternAwareLoss: mean over (B,S,L) of boost*mask*(softplus(x) - x*y) / sum(mask)
// B=64, S=8192, L=24. boost[b,s]=1.2 if any-label(s) && any-label(s+1) && s<S-1.
//
// R5: main loop was MUFU-bound (2 MUFU/elem = 42K cyc/SM ~ 24us) with 6x L1
// wavefront amplification from 96B-stride float4 loads.
//  - MUFU fix: sum(log1p(u)) = log(prod(1+u)); per elem 1 EX2 + 1 FFMA,
//    only 2 LG2 per position -> MUFU floor ~12.8us.
//  - Coalescing fix: scalar coalesced LDG -> smem staging. Logits stride-25
//    floats (conflict-free scalar LDS); labels packed to bytes stride-28
//    (word reads at 7t mod 32, conflict-free).
// Two-kernel form (fusion measured 2.4us slower in R4).

#define NPOS   (64 * 8192)     // B*S
#define S_LEN  8192
#define L_DIM  24
#define TPB    256
#define POSB   256             // positions per block
#define NBLK   (NPOS / POSB)   // 2048

__device__ float2 g_part[NBLK];

__global__ __launch_bounds__(TPB) void loss_main_kernel(
    const float* __restrict__ logits,
    const int*   __restrict__ labels,
    const float* __restrict__ attn_mask)
{
    __shared__ float    s_lg[POSB * 25];        // 25600 B, row stride 25 floats
    __shared__ unsigned s_lbw[POSB * 7];        //  7168 B, row stride 28 bytes
    __shared__ unsigned char s_hp[POSB];
    __shared__ float2   wsum[TPB / 32];

    const int t = threadIdx.x;
    const unsigned lane = t & 31u;
    const size_t base_pos = (size_t)blockIdx.x * POSB;

    const float* __restrict__ lgp = logits + base_pos * L_DIM;
    const int*   __restrict__ lbp = labels + base_pos * L_DIM;

    const float m = attn_mask[base_pos + t];

    // Halo: thread 255 needs has_punct of the next block's first position.
    int halo_or = 0;
    if (t == TPB - 1) {
        size_t np = base_pos + POSB;            // global next position
        if ((np & (size_t)(S_LEN - 1)) != 0) {  // same batch (false => s==S-1, no boost)
            const int4* nb = reinterpret_cast<const int4*>(labels + np * L_DIM);
#pragma unroll
            for (int i = 0; i < 6; i++) {
                int4 v = nb[i];
                halo_or |= (v.x | v.y | v.z | v.w);
            }
        }
    }

    // ── Stage: perfectly coalesced scalar loads -> padded smem. ──
    unsigned char* s_lbb = reinterpret_cast<unsigned char*>(s_lbw);
#pragma unroll
    for (int i = 0; i < L_DIM; i++) {
        unsigned idx = (unsigned)(i * TPB + t);     // 0..6143, lane-consecutive
        float fv = lgp[idx];
        int   lv = lbp[idx];
        unsigned d = idx / 24u;                      // position within block
        s_lg[idx + d]       = fv;                    // q*25 + r  ==  idx + q
        s_lbb[idx + 4u * d] = (unsigned char)(lv != 0); // q*28 + r == idx + 4q
    }
    __syncthreads();

    // ── Compute: one thread per position, conflict-free smem reads. ──
    unsigned wv[6];
#pragma unroll
    for (int j = 0; j < 6; j++) wv[j] = s_lbw[t * 7 + j];   // 7t mod 32: bank-free
    const unsigned orr = wv[0] | wv[1] | wv[2] | wv[3] | wv[4] | wv[5];
    const int hp = (orr != 0);
    s_hp[t] = (unsigned char)hp;

    const float* __restrict__ xr = s_lg + t * 25;           // 25t mod 32: bank-free
    float sm0 = 0.f, sm1 = 0.f;
    float p0 = 1.f, p1 = 1.f;       // products of (1 + exp(-|x|))

#pragma unroll
    for (int k = 0; k < L_DIM; k++) {
        float x = xr[k];
        bool  b = ((wv[k >> 2] >> ((k & 3) * 8)) & 1u) != 0;
        // max(x,0) - x*y  ==  y ? relu(-x) : relu(x)
        float r = b ? fmaxf(-x, 0.f) : fmaxf(x, 0.f);
        float u = __expf(-fabsf(x));                 // 1 FMUL(|.|,neg) + MUFU.EX2
        if (k & 1) { sm1 += r; p1 = fmaf(p1, u, p1); }
        else       { sm0 += r; p0 = fmaf(p0, u, p0); }
    }

    // sum(log1p) = ln2 * (log2(p0) + log2(p1)) -> only 2 MUFU.LG2 per position
    float sl = __log2f(p0) + __log2f(p1);
    float possum = fmaf(0.69314718055994531f, sl, sm0 + sm1);

    __syncthreads();                                  // s_hp ready
    const int hpn = (t < TPB - 1) ? (int)s_hp[t + 1] : (halo_or != 0);
    const int s_in_batch = (int)((base_pos + t) & (S_LEN - 1));
    const float boost = (s_in_batch != (S_LEN - 1) && hp && hpn) ? 1.2f : 1.0f;

    float num = m * boost * possum;
    float den = m;

    // warp reduce (pairwise, deterministic)
#pragma unroll
    for (int off = 16; off > 0; off >>= 1) {
        num += __shfl_down_sync(0xffffffffu, num, off);
        den += __shfl_down_sync(0xffffffffu, den, off);
    }
    if (lane == 0) wsum[t >> 5] = make_float2(num, den);
    __syncthreads();
    if (t == 0) {
        float n = 0.f, d = 0.f;
#pragma unroll
        for (int i = 0; i < TPB / 32; i++) { n += wsum[i].x; d += wsum[i].y; }
        g_part[blockIdx.x] = make_float2(n, d);
    }
}

__global__ __launch_bounds__(256) void loss_reduce_kernel(float* __restrict__ out)
{
    __shared__ double sn[256];
    __shared__ double sd[256];
    double n = 0.0, d = 0.0;
#pragma unroll
    for (int i = threadIdx.x; i < NBLK; i += 256) {   // 8 independent loads
        float2 v = g_part[i];
        n += (double)v.x;
        d += (double)v.y;
    }
    sn[threadIdx.x] = n;
    sd[threadIdx.x] = d;
    __syncthreads();
#pragma unroll
    for (int s = 128; s > 0; s >>= 1) {
        if (threadIdx.x < s) {
            sn[threadIdx.x] += sn[threadIdx.x + s];
            sd[threadIdx.x] += sd[threadIdx.x + s];
        }
        __syncthreads();
    }
    if (threadIdx.x == 0) out[0] = (float)(sn[0] / sd[0]);
}

extern "C" void kernel_launch(void* const* d_in, const int* in_sizes, int n_in,
                              void* d_out, int out_size)
{
    const float* logits = (const float*)d_in[0];
    const int*   labels = (const int*)d_in[1];
    const float* amask  = (const float*)d_in[2];
    float* out = (float*)d_out;

    loss_main_kernel<<<NBLK, TPB>>>(logits, labels, amask);
    loss_reduce_kernel<<<1, 256>>>(out);
}